// round 3
// baseline (speedup 1.0000x reference)
#include <cuda_runtime.h>
#include <math.h>

#define LL 2048
#define CCdim 2048
#define BB 4
#define DD 1024
#define ZZ 128
#define EE (2*DD+ZZ)   // 2176
#define M1 (LL*BB)     // 8192

// ---------------- scratch (device globals: allocation-free) ----------------
__device__ float g_x[M1*DD];        // LN output
__device__ float g_u[M1*DD];        // sigmoid gate
__device__ float g_r[M1*DD];        // silu gate
__device__ float g_q[M1*ZZ];        // q (pre-scaled)
__device__ float g_k[M1*ZZ];        // k
__device__ float g_v[M1*DD];        // silu(v)
__device__ float g_h[M1*DD];        // attn @ v
__device__ float g_a[LL*ZZ];        // rot(alpha)
__device__ float g_b[CCdim*ZZ];     // rot(beta)
__device__ float g_bias[LL*CCdim];  // rotary relative bias
__device__ float g_qk[(size_t)BB*LL*CCdim]; // scores / attn (in place)

__device__ __forceinline__ float sigmoidf_(float v){ return 1.f/(1.f+expf(-v)); }
__device__ __forceinline__ float siluf_(float v){ return v/(1.f+expf(-v)); }

// ---------------- LayerNorm: one block per row of D=1024 ----------------
__global__ void ln_kernel(const float* __restrict__ q, const float* __restrict__ w,
                          const float* __restrict__ b, float* __restrict__ x)
{
    int row = blockIdx.x;
    int tid = threadIdx.x;               // 256 threads, 1 float4 each
    const float4* p = (const float4*)(q + (size_t)row*DD);
    float4 v = p[tid];
    float s  = v.x+v.y+v.z+v.w;
    float ss = v.x*v.x+v.y*v.y+v.z*v.z+v.w*v.w;
    #pragma unroll
    for (int o=16;o;o>>=1){ s += __shfl_xor_sync(~0u,s,o); ss += __shfl_xor_sync(~0u,ss,o); }
    __shared__ float shA[8], shB[8];
    int warp = tid>>5, lane = tid&31;
    if (lane==0){ shA[warp]=s; shB[warp]=ss; }
    __syncthreads();
    float tots=0.f, totss=0.f;
    #pragma unroll
    for (int wdx=0; wdx<8; ++wdx){ tots += shA[wdx]; totss += shB[wdx]; }
    float mean = tots*(1.f/DD);
    float var  = totss*(1.f/DD) - mean*mean;
    float rstd = rsqrtf(var + 1e-5f);
    float4 w4 = ((const float4*)w)[tid];
    float4 b4 = ((const float4*)b)[tid];
    float4 o;
    o.x = (v.x-mean)*rstd*w4.x + b4.x;
    o.y = (v.y-mean)*rstd*w4.y + b4.y;
    o.z = (v.z-mean)*rstd*w4.z + b4.z;
    o.w = (v.w-mean)*rstd*w4.w + b4.w;
    ((float4*)(x + (size_t)row*DD))[tid] = o;
}

// ---------------- rotary rot(alpha)/rot(beta): (2048,128) each ----------------
__global__ void rotab_kernel(const float* __restrict__ alpha, const float* __restrict__ beta)
{
    int m = blockIdx.x;        // 0..2047
    int i = threadIdx.x;       // 0..63
    float f = expf((float)i * (-9.210340371976184f / 64.f)); // -log(10000)/half
    float ang = (float)m * f;
    float s, c;
    sincosf(ang, &s, &c);
    float a1 = alpha[i], a2 = alpha[i+64];
    g_a[m*ZZ + i]      = a1*c - a2*s;
    g_a[m*ZZ + i + 64] = a2*c + a1*s;
    float b1 = beta[i],  b2 = beta[i+64];
    g_b[m*ZZ + i]      = b1*c - b2*s;
    g_b[m*ZZ + i + 64] = b2*c + b1*s;
}

// ---------------- softmax over C with fused rotary bias ----------------
__global__ void softmax_kernel()
{
    long row = blockIdx.x;                    // b*L + l
    int  l   = (int)(row & (LL-1));
    float* p = g_qk + row * (long)CCdim;
    const float* bp = g_bias + (long)l * CCdim;
    int tid = threadIdx.x;                    // 256 threads * 8 elems
    float4 v0 = ((const float4*)p)[tid];
    float4 v1 = ((const float4*)p)[tid+256];
    float4 b0 = ((const float4*)bp)[tid];
    float4 b1 = ((const float4*)bp)[tid+256];
    float e0 = v0.x+b0.x, e1 = v0.y+b0.y, e2 = v0.z+b0.z, e3 = v0.w+b0.w;
    float e4 = v1.x+b1.x, e5 = v1.y+b1.y, e6 = v1.z+b1.z, e7 = v1.w+b1.w;
    float mx = fmaxf(fmaxf(fmaxf(e0,e1),fmaxf(e2,e3)), fmaxf(fmaxf(e4,e5),fmaxf(e6,e7)));
    #pragma unroll
    for (int o=16;o;o>>=1) mx = fmaxf(mx, __shfl_xor_sync(~0u,mx,o));
    __shared__ float shm[8], shs[8];
    int warp = tid>>5, lane = tid&31;
    if (lane==0) shm[warp] = mx;
    __syncthreads();
    mx = shm[0];
    #pragma unroll
    for (int wdx=1; wdx<8; ++wdx) mx = fmaxf(mx, shm[wdx]);
    e0 = expf(e0-mx); e1 = expf(e1-mx); e2 = expf(e2-mx); e3 = expf(e3-mx);
    e4 = expf(e4-mx); e5 = expf(e5-mx); e6 = expf(e6-mx); e7 = expf(e7-mx);
    float s = e0+e1+e2+e3+e4+e5+e6+e7;
    #pragma unroll
    for (int o=16;o;o>>=1) s += __shfl_xor_sync(~0u,s,o);
    if (lane==0) shs[warp] = s;
    __syncthreads();
    s = 0.f;
    #pragma unroll
    for (int wdx=0; wdx<8; ++wdx) s += shs[wdx];
    float inv = 1.f/s;
    float4 o0 = make_float4(e0*inv, e1*inv, e2*inv, e3*inv);
    float4 o1 = make_float4(e4*inv, e5*inv, e6*inv, e7*inv);
    ((float4*)p)[tid]     = o0;
    ((float4*)p)[tid+256] = o1;
}

// ---------------- generic 128x128x16 SGEMM, 8x8 per thread ----------------
// MODE 0: base proj  -> writes g_u (sigmoid) / g_r (silu) / g_q (scaled), bias=aux1
// MODE 1: plain store to Cout
// MODE 2: store + bias vector aux1
// MODE 3: silu(store + aux1)
// MODE 4: final gate: out = res + u*(silu(acc+bh) - res); aux1=bh, aux2=query; u from g_u
// BT: true => B operand is N-major (NxK row-major, "NT" gemm); false => KxN ("NN")
// MULA: multiply A tile elementwise by g_r at the same offsets (final GEMM)
template<int MODE, bool BT, bool MULA>
__global__ void __launch_bounds__(256, 2)
gemm_k(const float* __restrict__ A, const float* __restrict__ Bm,
       int K, int lda, int ldb, long sAz, long sBz,
       float* __restrict__ Cout, int ldc, long sCz,
       const float* __restrict__ aux1, const float* __restrict__ aux2)
{
    __shared__ float As[16][128];
    __shared__ float Bs[16][128];
    int bz = blockIdx.z;
    A    += (long)bz * sAz;
    Bm   += (long)bz * sBz;
    Cout += (long)bz * sCz;
    long a2off = (long)bz * sAz;   // g_r shares A's addressing (only used when MULA)

    int m0 = blockIdx.y << 7, n0 = blockIdx.x << 7;
    int tid = threadIdx.x;
    int tx = tid & 15, ty = tid >> 4;

    float acc[8][8];
    #pragma unroll
    for (int i=0;i<8;++i)
        #pragma unroll
        for (int j=0;j<8;++j) acc[i][j] = 0.f;

    for (int k0=0; k0<K; k0+=16) {
        #pragma unroll
        for (int it=0; it<2; ++it) {
            int f = tid + (it<<8);
            int r = f >> 2, c4 = (f & 3) << 2;
            float4 v = *(const float4*)(A + (long)(m0+r)*lda + (k0+c4));
            if (MULA) {
                float4 v2 = *(const float4*)(g_r + a2off + (long)(m0+r)*lda + (k0+c4));
                v.x*=v2.x; v.y*=v2.y; v.z*=v2.z; v.w*=v2.w;
            }
            As[c4+0][r]=v.x; As[c4+1][r]=v.y; As[c4+2][r]=v.z; As[c4+3][r]=v.w;
        }
        #pragma unroll
        for (int it=0; it<2; ++it) {
            int f = tid + (it<<8);
            if (BT) {
                int r = f >> 2, c4 = (f & 3) << 2;
                float4 v = *(const float4*)(Bm + (long)(n0+r)*ldb + (k0+c4));
                Bs[c4+0][r]=v.x; Bs[c4+1][r]=v.y; Bs[c4+2][r]=v.z; Bs[c4+3][r]=v.w;
            } else {
                int kk = f >> 5, c4 = (f & 31) << 2;
                *(float4*)&Bs[kk][c4] = *(const float4*)(Bm + (long)(k0+kk)*ldb + (n0+c4));
            }
        }
        __syncthreads();
        #pragma unroll
        for (int kk=0; kk<16; ++kk) {
            float ra[8], rb[8];
            *(float4*)&ra[0] = *(const float4*)&As[kk][(ty<<3)+0];
            *(float4*)&ra[4] = *(const float4*)&As[kk][(ty<<3)+4];
            *(float4*)&rb[0] = *(const float4*)&Bs[kk][(tx<<3)+0];
            *(float4*)&rb[4] = *(const float4*)&Bs[kk][(tx<<3)+4];
            #pragma unroll
            for (int i=0;i<8;++i)
                #pragma unroll
                for (int j=0;j<8;++j)
                    acc[i][j] += ra[i]*rb[j];
        }
        __syncthreads();
    }

    #pragma unroll
    for (int i=0;i<8;++i) {
        int m = m0 + (ty<<3) + i;
        #pragma unroll
        for (int j=0;j<8;++j) {
            int n = n0 + (tx<<3) + j;
            float v = acc[i][j];
            if (MODE==0) {
                v += aux1[n];
                if (n < DD)            g_u[(long)m*DD + n]        = sigmoidf_(v);
                else if (n < 2*DD)     g_r[(long)m*DD + (n-DD)]   = siluf_(v);
                else                   g_q[(long)m*ZZ + (n-2*DD)] = v * 0.08838834764831845f; // Z^-0.5
            } else if (MODE==1) {
                Cout[(long)m*ldc + n] = v;
            } else if (MODE==2) {
                Cout[(long)m*ldc + n] = v + aux1[n];
            } else if (MODE==3) {
                Cout[(long)m*ldc + n] = siluf_(v + aux1[n]);
            } else { // MODE 4
                float t = siluf_(v + aux1[n]);
                long idx = (long)m*DD + n;
                float res = aux2[idx];
                float uu  = g_u[idx];
                Cout[idx] = res + uu*(t - res);
            }
        }
    }
}

// ---------------- launch ----------------
extern "C" void kernel_launch(void* const* d_in, const int* in_sizes, int n_in,
                              void* d_out, int out_size)
{
    const float* query   = (const float*)d_in[0];
    const float* key_seq = (const float*)d_in[1];
    const float* value   = (const float*)d_in[2];
    const float* wq      = (const float*)d_in[3];
    const float* bq      = (const float*)d_in[4];
    const float* wk      = (const float*)d_in[5];
    const float* bk      = (const float*)d_in[6];
    const float* wv      = (const float*)d_in[7];
    const float* bv      = (const float*)d_in[8];
    const float* wh      = (const float*)d_in[9];
    const float* bh      = (const float*)d_in[10];
    const float* ln_w    = (const float*)d_in[11];
    const float* ln_b    = (const float*)d_in[12];
    const float* alpha   = (const float*)d_in[13];
    const float* beta    = (const float*)d_in[14];
    float* out = (float*)d_out;

    float *p_x, *p_q, *p_k, *p_v, *p_h, *p_a, *p_b, *p_bias, *p_qk;
    cudaGetSymbolAddress((void**)&p_x,   g_x);
    cudaGetSymbolAddress((void**)&p_q,   g_q);
    cudaGetSymbolAddress((void**)&p_k,   g_k);
    cudaGetSymbolAddress((void**)&p_v,   g_v);
    cudaGetSymbolAddress((void**)&p_h,   g_h);
    cudaGetSymbolAddress((void**)&p_a,   g_a);
    cudaGetSymbolAddress((void**)&p_b,   g_b);
    cudaGetSymbolAddress((void**)&p_bias,g_bias);
    cudaGetSymbolAddress((void**)&p_qk,  g_qk);

    // 1. LayerNorm
    ln_kernel<<<M1, 256>>>(query, ln_w, ln_b, p_x);
    // 2. rotary a/b tables
    rotab_kernel<<<LL, 64>>>(alpha, beta);
    // 3. base projection: u / r / q  (8192 x 2176 x 1024)
    gemm_k<0,true,false><<<dim3(EE/128, M1/128, 1), 256>>>(
        p_x, wq, DD, DD, DD, 0, 0, nullptr, 0, 0, bq, nullptr);
    // 4. k projection (8192 x 128 x 1024)
    gemm_k<2,true,false><<<dim3(1, M1/128, 1), 256>>>(
        key_seq, wk, DD, DD, DD, 0, 0, p_k, ZZ, 0, bk, nullptr);
    // 5. v projection + silu (8192 x 1024 x 1024)
    gemm_k<3,true,false><<<dim3(DD/128, M1/128, 1), 256>>>(
        value, wv, DD, DD, DD, 0, 0, p_v, DD, 0, bv, nullptr);
    // 6. rotary bias matrix (2048 x 2048 x 128)
    gemm_k<1,true,false><<<dim3(CCdim/128, LL/128, 1), 256>>>(
        p_a, p_b, ZZ, ZZ, ZZ, 0, 0, p_bias, CCdim, 0, nullptr, nullptr);
    // 7. QK^T batched over B (2048 x 2048 x 128 per batch)
    gemm_k<1,true,false><<<dim3(CCdim/128, LL/128, BB), 256>>>(
        p_q, p_k, ZZ, BB*ZZ, BB*ZZ, (long)ZZ, (long)ZZ,
        p_qk, CCdim, (long)LL*CCdim, nullptr, nullptr);
    // 8. softmax with fused bias (in place on g_qk)
    softmax_kernel<<<BB*LL, 256>>>();
    // 9. attn @ v batched (2048 x 1024 x 2048 per batch) — NN gemm
    gemm_k<1,false,false><<<dim3(DD/128, LL/128, BB), 256>>>(
        p_qk, p_v, CCdim, CCdim, BB*DD, (long)LL*CCdim, (long)DD,
        p_h, BB*DD, (long)DD, nullptr, nullptr);
    // 10. output projection with fused h*r, silu, and gated residual
    gemm_k<4,true,true><<<dim3(DD/128, M1/128, 1), 256>>>(
        p_h, wh, DD, DD, DD, 0, 0, out, DD, 0, bh, query);
}

// round 5
// speedup vs baseline: 2.0237x; 2.0237x over previous
#include <cuda_runtime.h>
#include <math.h>
#include <stdint.h>

#define LL 2048
#define CCdim 2048
#define BB 4
#define DD 1024
#define ZZ 128
#define EE (2*DD+ZZ)   // 2176
#define M1 (LL*BB)     // 8192

// ---------------- scratch (device globals: allocation-free) ----------------
__device__ float g_x[M1*DD];        // LN output
__device__ float g_u[M1*DD];        // sigmoid gate
__device__ float g_r[M1*DD];        // silu gate
__device__ float g_q[M1*ZZ];        // q (pre-scaled)
__device__ float g_k[M1*ZZ];        // k
__device__ float g_v[M1*DD];        // silu(v)
__device__ float g_h[M1*DD];        // attn @ v
__device__ float g_a[LL*ZZ];        // rot(alpha)
__device__ float g_b[CCdim*ZZ];     // rot(beta)
__device__ float g_bias[LL*CCdim];  // rotary relative bias
__device__ float g_qk[(size_t)BB*LL*CCdim]; // scores / attn (in place)

__device__ __forceinline__ float sigmoidf_(float v){ return 1.f/(1.f+expf(-v)); }
__device__ __forceinline__ float siluf_(float v){ return v/(1.f+expf(-v)); }

// round fp32 -> tf32 (RN) so mma truncation doesn't cost extra accuracy
__device__ __forceinline__ float tfr(float x){
    uint32_t u; asm("cvt.rna.tf32.f32 %0, %1;" : "=r"(u) : "f"(x));
    return __uint_as_float(u);
}

__device__ __forceinline__ void mma8(float c[4], const uint32_t a[4], const uint32_t b[2]){
    asm volatile("mma.sync.aligned.m16n8k8.row.col.f32.tf32.tf32.f32 "
        "{%0,%1,%2,%3}, {%4,%5,%6,%7}, {%8,%9}, {%0,%1,%2,%3};\n"
        : "+f"(c[0]), "+f"(c[1]), "+f"(c[2]), "+f"(c[3])
        : "r"(a[0]), "r"(a[1]), "r"(a[2]), "r"(a[3]), "r"(b[0]), "r"(b[1]));
}

// ---------------- LayerNorm: one block per row of D=1024 ----------------
__global__ void ln_kernel(const float* __restrict__ q, const float* __restrict__ w,
                          const float* __restrict__ b, float* __restrict__ x)
{
    int row = blockIdx.x;
    int tid = threadIdx.x;
    const float4* p = (const float4*)(q + (size_t)row*DD);
    float4 v = p[tid];
    float s  = v.x+v.y+v.z+v.w;
    float ss = v.x*v.x+v.y*v.y+v.z*v.z+v.w*v.w;
    #pragma unroll
    for (int o=16;o;o>>=1){ s += __shfl_xor_sync(~0u,s,o); ss += __shfl_xor_sync(~0u,ss,o); }
    __shared__ float shA[8], shB[8];
    int warp = tid>>5, lane = tid&31;
    if (lane==0){ shA[warp]=s; shB[warp]=ss; }
    __syncthreads();
    float tots=0.f, totss=0.f;
    #pragma unroll
    for (int wdx=0; wdx<8; ++wdx){ tots += shA[wdx]; totss += shB[wdx]; }
    float mean = tots*(1.f/DD);
    float var  = totss*(1.f/DD) - mean*mean;
    float rstd = rsqrtf(var + 1e-5f);
    float4 w4 = ((const float4*)w)[tid];
    float4 b4 = ((const float4*)b)[tid];
    float4 o;
    o.x = (v.x-mean)*rstd*w4.x + b4.x;
    o.y = (v.y-mean)*rstd*w4.y + b4.y;
    o.z = (v.z-mean)*rstd*w4.z + b4.z;
    o.w = (v.w-mean)*rstd*w4.w + b4.w;
    ((float4*)(x + (size_t)row*DD))[tid] = o;
}

// ---------------- rotary rot(alpha)/rot(beta) ----------------
__global__ void rotab_kernel(const float* __restrict__ alpha, const float* __restrict__ beta)
{
    int m = blockIdx.x;
    int i = threadIdx.x;
    float f = expf((float)i * (-9.210340371976184f / 64.f));
    float ang = (float)m * f;
    float s, c;
    sincosf(ang, &s, &c);
    float a1 = alpha[i], a2 = alpha[i+64];
    g_a[m*ZZ + i]      = a1*c - a2*s;
    g_a[m*ZZ + i + 64] = a2*c + a1*s;
    float b1 = beta[i],  b2 = beta[i+64];
    g_b[m*ZZ + i]      = b1*c - b2*s;
    g_b[m*ZZ + i + 64] = b2*c + b1*s;
}

// ---------------- softmax over C with fused rotary bias ----------------
__global__ void softmax_kernel()
{
    long row = blockIdx.x;
    int  l   = (int)(row & (LL-1));
    float* p = g_qk + row * (long)CCdim;
    const float* bp = g_bias + (long)l * CCdim;
    int tid = threadIdx.x;
    float4 v0 = ((const float4*)p)[tid];
    float4 v1 = ((const float4*)p)[tid+256];
    float4 b0 = ((const float4*)bp)[tid];
    float4 b1 = ((const float4*)bp)[tid+256];
    float e0 = v0.x+b0.x, e1 = v0.y+b0.y, e2 = v0.z+b0.z, e3 = v0.w+b0.w;
    float e4 = v1.x+b1.x, e5 = v1.y+b1.y, e6 = v1.z+b1.z, e7 = v1.w+b1.w;
    float mx = fmaxf(fmaxf(fmaxf(e0,e1),fmaxf(e2,e3)), fmaxf(fmaxf(e4,e5),fmaxf(e6,e7)));
    #pragma unroll
    for (int o=16;o;o>>=1) mx = fmaxf(mx, __shfl_xor_sync(~0u,mx,o));
    __shared__ float shm[8], shs[8];
    int warp = tid>>5, lane = tid&31;
    if (lane==0) shm[warp] = mx;
    __syncthreads();
    mx = shm[0];
    #pragma unroll
    for (int wdx=1; wdx<8; ++wdx) mx = fmaxf(mx, shm[wdx]);
    e0 = expf(e0-mx); e1 = expf(e1-mx); e2 = expf(e2-mx); e3 = expf(e3-mx);
    e4 = expf(e4-mx); e5 = expf(e5-mx); e6 = expf(e6-mx); e7 = expf(e7-mx);
    float s = e0+e1+e2+e3+e4+e5+e6+e7;
    #pragma unroll
    for (int o=16;o;o>>=1) s += __shfl_xor_sync(~0u,s,o);
    if (lane==0) shs[warp] = s;
    __syncthreads();
    s = 0.f;
    #pragma unroll
    for (int wdx=0; wdx<8; ++wdx) s += shs[wdx];
    float inv = 1.f/s;
    ((float4*)p)[tid]     = make_float4(e0*inv, e1*inv, e2*inv, e3*inv);
    ((float4*)p)[tid+256] = make_float4(e4*inv, e5*inv, e6*inv, e7*inv);
}

// ---------------- TF32 tensor-core GEMM, 128x128x16, 8 warps ----------------
// Smem tiles are stored in mma-FRAGMENT order so fragment reads are
// conflict-free LDS.128 / LDS.64. Conversion to tf32 happens once at staging.
//
// A frag layout:  [ks(2)][m16(8)][lane(32)][reg(4)]   (2048 floats / buffer)
//   element (m,k): lane=(m%8)*4+(k%4), reg=((k%8)/4)*2+((m%16)/8)
// B frag layout:  [ks(2)][n8(16)][lane(32)][reg(2)]   (2048 floats / buffer)
//   element (n,k): lane=(n%8)*4+(k%4), reg=(k%8)/4
//
// MODE / BT / MULA semantics identical to the previous fp32 kernel.
template<int MODE, bool BT, bool MULA>
__global__ void __launch_bounds__(256, 2)
gemm_tc(const float* __restrict__ A, const float* __restrict__ Bm,
        int K, int lda, int ldb, long sAz, long sBz,
        float* __restrict__ Cout, int ldc, long sCz,
        const float* __restrict__ aux1, const float* __restrict__ aux2)
{
    __shared__ float As[2*2048];
    __shared__ float Bs[2*2048];

    const int bz = blockIdx.z;
    A    += (long)bz * sAz;
    Bm   += (long)bz * sBz;
    Cout += (long)bz * sCz;
    const float* Rm = MULA ? (g_r + (long)bz * sAz) : (const float*)nullptr;

    const int m0 = blockIdx.y << 7, n0 = blockIdx.x << 7;
    const int tid = threadIdx.x, lane = tid & 31, wid = tid >> 5;
    const int wm4 = (wid >> 2) << 2;   // m16-tile base (0 or 4)
    const int wn4 = (wid & 3) << 2;    // n8-tile base (0,4,8,12)

    float acc[4][4][4];
    #pragma unroll
    for (int i=0;i<4;++i)
        #pragma unroll
        for (int j=0;j<4;++j)
            #pragma unroll
            for (int c=0;c<4;++c) acc[i][j][c] = 0.f;

    // ---- A loader: thread -> (row ar / ar+64, k4) float4 ----
    const int ar  = tid >> 2;
    const int ak4 = (tid & 3) << 2;
    const float* apA0 = A + (long)(m0 + ar) * lda + ak4;
    const float* apA1 = apA0 + (long)64 * lda;
    const float* apR0 = MULA ? (Rm + (long)(m0 + ar) * lda + ak4) : (const float*)nullptr;
    const float* apR1 = MULA ? (apR0 + (long)64 * lda) : (const float*)nullptr;
    const int aks  = ak4 >> 3;
    const int abase0 = (aks*8 + (ar>>4))*128 + (ar&7)*16 + (((ak4&7)>>2)<<1) + ((ar&15)>>3);
    const int abase1 = abase0 + 4*128;   // rows +64 -> m16 +4

    // ---- B loader ----
    const float *bp0 = nullptr, *bp1 = nullptr, *bpN = nullptr;
    int bbase0 = 0, bbase1 = 0, bnbase = 0;
    if (BT) {
        const int br  = tid >> 2;          // n
        const int bk4 = (tid & 3) << 2;
        bp0 = Bm + (long)(n0 + br) * ldb + bk4;
        bp1 = bp0 + (long)64 * ldb;
        bbase0 = ((bk4>>3)*16 + (br>>3))*64 + (br&7)*8 + ((bk4&7)>>2);
        bbase1 = bbase0 + 8*64;            // n +64 -> n8 +8
    } else {
        const int nn = tid & 127;
        const int kb = (tid >> 7) << 3;    // 0 or 8
        bpN = Bm + (long)kb * ldb + n0 + nn;
        bnbase = ((kb>>3)*16 + (nn>>3))*64 + (nn&7)*8;
    }

    float4 va0, va1, vb0, vb1; float vbn[8];

    auto loadg = [&](int kg){
        va0 = *(const float4*)(apA0 + kg);
        va1 = *(const float4*)(apA1 + kg);
        if (MULA) {
            float4 r0 = *(const float4*)(apR0 + kg);
            float4 r1 = *(const float4*)(apR1 + kg);
            va0.x*=r0.x; va0.y*=r0.y; va0.z*=r0.z; va0.w*=r0.w;
            va1.x*=r1.x; va1.y*=r1.y; va1.z*=r1.z; va1.w*=r1.w;
        }
        if (BT) {
            vb0 = *(const float4*)(bp0 + kg);
            vb1 = *(const float4*)(bp1 + kg);
        } else {
            const float* p = bpN + (long)kg * ldb;
            #pragma unroll
            for (int j=0;j<8;++j){ vbn[j] = *p; p += ldb; }
        }
    };

    auto stores = [&](int b){
        float* sA = As + b*2048;
        float* sB = Bs + b*2048;
        sA[abase0+ 0]=tfr(va0.x); sA[abase0+ 4]=tfr(va0.y);
        sA[abase0+ 8]=tfr(va0.z); sA[abase0+12]=tfr(va0.w);
        sA[abase1+ 0]=tfr(va1.x); sA[abase1+ 4]=tfr(va1.y);
        sA[abase1+ 8]=tfr(va1.z); sA[abase1+12]=tfr(va1.w);
        if (BT) {
            sB[bbase0+0]=tfr(vb0.x); sB[bbase0+2]=tfr(vb0.y);
            sB[bbase0+4]=tfr(vb0.z); sB[bbase0+6]=tfr(vb0.w);
            sB[bbase1+0]=tfr(vb1.x); sB[bbase1+2]=tfr(vb1.y);
            sB[bbase1+4]=tfr(vb1.z); sB[bbase1+6]=tfr(vb1.w);
        } else {
            #pragma unroll
            for (int j=0;j<8;++j)
                sB[bnbase + (j&3)*2 + (j>>2)] = tfr(vbn[j]);
        }
    };

    auto comp = [&](int b){
        const float* sA = As + b*2048;
        const float* sB = Bs + b*2048;
        #pragma unroll
        for (int ks=0; ks<2; ++ks) {
            uint4 af[4]; uint2 bf[4];
            #pragma unroll
            for (int mt=0; mt<4; ++mt)
                af[mt] = *(const uint4*)(sA + (ks*8 + wm4 + mt)*128 + lane*4);
            #pragma unroll
            for (int nt=0; nt<4; ++nt)
                bf[nt] = *(const uint2*)(sB + (ks*16 + wn4 + nt)*64 + lane*2);
            #pragma unroll
            for (int mt=0; mt<4; ++mt)
                #pragma unroll
                for (int nt=0; nt<4; ++nt)
                    mma8(acc[mt][nt], (const uint32_t*)&af[mt], (const uint32_t*)&bf[nt]);
        }
    };

    loadg(0);
    stores(0);
    __syncthreads();
    int buf = 0;
    for (int kg = 16; kg < K; kg += 16) {
        loadg(kg);
        comp(buf);
        stores(buf ^ 1);
        __syncthreads();
        buf ^= 1;
    }
    comp(buf);

    // ---- epilogue ----
    #pragma unroll
    for (int mt=0; mt<4; ++mt) {
        #pragma unroll
        for (int ci2=0; ci2<2; ++ci2) {
            int m = m0 + (wm4+mt)*16 + (lane>>2) + ci2*8;
            #pragma unroll
            for (int nt=0; nt<4; ++nt) {
                #pragma unroll
                for (int cj=0; cj<2; ++cj) {
                    int n = n0 + (wn4+nt)*8 + ((lane&3)<<1) + cj;
                    float v = acc[mt][nt][ci2*2+cj];
                    if (MODE==0) {
                        v += aux1[n];
                        if (n < DD)            g_u[(long)m*DD + n]        = sigmoidf_(v);
                        else if (n < 2*DD)     g_r[(long)m*DD + (n-DD)]   = siluf_(v);
                        else                   g_q[(long)m*ZZ + (n-2*DD)] = v * 0.08838834764831845f;
                    } else if (MODE==1) {
                        Cout[(long)m*ldc + n] = v;
                    } else if (MODE==2) {
                        Cout[(long)m*ldc + n] = v + aux1[n];
                    } else if (MODE==3) {
                        Cout[(long)m*ldc + n] = siluf_(v + aux1[n]);
                    } else {
                        float t = siluf_(v + aux1[n]);
                        long idx = (long)m*DD + n;
                        float res = aux2[idx];
                        Cout[idx] = res + g_u[idx]*(t - res);
                    }
                }
            }
        }
    }
}

// ---------------- launch ----------------
extern "C" void kernel_launch(void* const* d_in, const int* in_sizes, int n_in,
                              void* d_out, int out_size)
{
    const float* query   = (const float*)d_in[0];
    const float* key_seq = (const float*)d_in[1];
    const float* value   = (const float*)d_in[2];
    const float* wq      = (const float*)d_in[3];
    const float* bq      = (const float*)d_in[4];
    const float* wk      = (const float*)d_in[5];
    const float* bk      = (const float*)d_in[6];
    const float* wv      = (const float*)d_in[7];
    const float* bv      = (const float*)d_in[8];
    const float* wh      = (const float*)d_in[9];
    const float* bh      = (const float*)d_in[10];
    const float* ln_w    = (const float*)d_in[11];
    const float* ln_b    = (const float*)d_in[12];
    const float* alpha   = (const float*)d_in[13];
    const float* beta    = (const float*)d_in[14];
    float* out = (float*)d_out;

    float *p_x, *p_q, *p_k, *p_v, *p_h, *p_a, *p_b, *p_bias, *p_qk;
    cudaGetSymbolAddress((void**)&p_x,   g_x);
    cudaGetSymbolAddress((void**)&p_q,   g_q);
    cudaGetSymbolAddress((void**)&p_k,   g_k);
    cudaGetSymbolAddress((void**)&p_v,   g_v);
    cudaGetSymbolAddress((void**)&p_h,   g_h);
    cudaGetSymbolAddress((void**)&p_a,   g_a);
    cudaGetSymbolAddress((void**)&p_b,   g_b);
    cudaGetSymbolAddress((void**)&p_bias,g_bias);
    cudaGetSymbolAddress((void**)&p_qk,  g_qk);

    // 1. LayerNorm
    ln_kernel<<<M1, 256>>>(query, ln_w, ln_b, p_x);
    // 2. rotary a/b tables
    rotab_kernel<<<LL, 64>>>(alpha, beta);
    // 3. base projection: u / r / q  (8192 x 2176 x 1024)
    gemm_tc<0,true,false><<<dim3(EE/128, M1/128, 1), 256>>>(
        p_x, wq, DD, DD, DD, 0, 0, nullptr, 0, 0, bq, nullptr);
    // 4. k projection (8192 x 128 x 1024)
    gemm_tc<2,true,false><<<dim3(1, M1/128, 1), 256>>>(
        key_seq, wk, DD, DD, DD, 0, 0, p_k, ZZ, 0, bk, nullptr);
    // 5. v projection + silu (8192 x 1024 x 1024)
    gemm_tc<3,true,false><<<dim3(DD/128, M1/128, 1), 256>>>(
        value, wv, DD, DD, DD, 0, 0, p_v, DD, 0, bv, nullptr);
    // 6. rotary bias matrix (2048 x 2048 x 128)
    gemm_tc<1,true,false><<<dim3(CCdim/128, LL/128, 1), 256>>>(
        p_a, p_b, ZZ, ZZ, ZZ, 0, 0, p_bias, CCdim, 0, nullptr, nullptr);
    // 7. QK^T batched over B (2048 x 2048 x 128 per batch)
    gemm_tc<1,true,false><<<dim3(CCdim/128, LL/128, BB), 256>>>(
        p_q, p_k, ZZ, BB*ZZ, BB*ZZ, (long)ZZ, (long)ZZ,
        p_qk, CCdim, (long)LL*CCdim, nullptr, nullptr);
    // 8. softmax with fused bias (in place on g_qk)
    softmax_kernel<<<BB*LL, 256>>>();
    // 9. attn @ v batched (2048 x 1024 x 2048 per batch) — NN gemm
    gemm_tc<1,false,false><<<dim3(DD/128, LL/128, BB), 256>>>(
        p_qk, p_v, CCdim, CCdim, BB*DD, (long)LL*CCdim, (long)DD,
        p_h, BB*DD, (long)DD, nullptr, nullptr);
    // 10. output projection with fused h*r, silu, and gated residual
    gemm_tc<4,true,true><<<dim3(DD/128, M1/128, 1), 256>>>(
        p_h, wh, DD, DD, DD, 0, 0, out, DD, 0, bh, query);
}

// round 7
// speedup vs baseline: 3.5008x; 1.7299x over previous
#include <cuda_runtime.h>
#include <math.h>
#include <stdint.h>

#define LL 2048
#define CCdim 2048
#define BB 4
#define DD 1024
#define ZZ 128
#define EE (2*DD+ZZ)   // 2176
#define M1 (LL*BB)     // 8192

#define STAGES 4
#define SMEM_BYTES (STAGES*2048*2*4)   // 64 KB: A + B stages

// ---------------- scratch (device globals: allocation-free) ----------------
__device__ float g_x[M1*DD];        // LN output, later h*r product
__device__ float g_u[M1*DD];        // sigmoid gate
__device__ float g_r[M1*DD];        // silu gate
__device__ float g_q[M1*ZZ];        // q (pre-scaled, tf32-rounded)
__device__ float g_k[M1*ZZ];        // k (tf32-rounded)
__device__ float g_v[M1*DD];        // silu(v) (tf32-rounded)
__device__ float g_h[M1*DD];        // attn @ v
__device__ float g_a[LL*ZZ];        // rot(alpha)
__device__ float g_b[CCdim*ZZ];     // rot(beta)
__device__ float g_bias[LL*CCdim];  // rotary relative bias
__device__ float g_qk[(size_t)BB*LL*CCdim]; // scores / attn (in place)

__device__ __forceinline__ float sigmoidf_(float v){ return 1.f/(1.f+expf(-v)); }
__device__ __forceinline__ float siluf_(float v){ return v/(1.f+expf(-v)); }

// round fp32 -> tf32 (RNA) at producers so mma truncation costs nothing extra
__device__ __forceinline__ float tfr(float x){
    uint32_t u; asm("cvt.rna.tf32.f32 %0, %1;" : "=r"(u) : "f"(x));
    return __uint_as_float(u);
}

__device__ __forceinline__ void mma8(float c[4], const uint32_t a[4], const uint32_t b[2]){
    asm volatile("mma.sync.aligned.m16n8k8.row.col.f32.tf32.tf32.f32 "
        "{%0,%1,%2,%3}, {%4,%5,%6,%7}, {%8,%9}, {%0,%1,%2,%3};\n"
        : "+f"(c[0]), "+f"(c[1]), "+f"(c[2]), "+f"(c[3])
        : "r"(a[0]), "r"(a[1]), "r"(a[2]), "r"(a[3]), "r"(b[0]), "r"(b[1]));
}

__device__ __forceinline__ void cpa16(uint32_t s, const float* g){
    asm volatile("cp.async.cg.shared.global [%0], [%1], 16;\n" :: "r"(s), "l"(g));
}
__device__ __forceinline__ void cpa_commit(){ asm volatile("cp.async.commit_group;\n"); }
template<int N>
__device__ __forceinline__ void cpa_wait(){ asm volatile("cp.async.wait_group %0;\n" :: "n"(N)); }

// ---------------- LayerNorm ----------------
__global__ void ln_kernel(const float* __restrict__ q, const float* __restrict__ w,
                          const float* __restrict__ b, float* __restrict__ x)
{
    int row = blockIdx.x;
    int tid = threadIdx.x;
    const float4* p = (const float4*)(q + (size_t)row*DD);
    float4 v = p[tid];
    float s  = v.x+v.y+v.z+v.w;
    float ss = v.x*v.x+v.y*v.y+v.z*v.z+v.w*v.w;
    #pragma unroll
    for (int o=16;o;o>>=1){ s += __shfl_xor_sync(~0u,s,o); ss += __shfl_xor_sync(~0u,ss,o); }
    __shared__ float shA[8], shB[8];
    int warp = tid>>5, lane = tid&31;
    if (lane==0){ shA[warp]=s; shB[warp]=ss; }
    __syncthreads();
    float tots=0.f, totss=0.f;
    #pragma unroll
    for (int wdx=0; wdx<8; ++wdx){ tots += shA[wdx]; totss += shB[wdx]; }
    float mean = tots*(1.f/DD);
    float var  = totss*(1.f/DD) - mean*mean;
    float rstd = rsqrtf(var + 1e-5f);
    float4 w4 = ((const float4*)w)[tid];
    float4 b4 = ((const float4*)b)[tid];
    float4 o;
    o.x = tfr((v.x-mean)*rstd*w4.x + b4.x);
    o.y = tfr((v.y-mean)*rstd*w4.y + b4.y);
    o.z = tfr((v.z-mean)*rstd*w4.z + b4.z);
    o.w = tfr((v.w-mean)*rstd*w4.w + b4.w);
    ((float4*)(x + (size_t)row*DD))[tid] = o;
}

// ---------------- rotary tables ----------------
__global__ void rotab_kernel(const float* __restrict__ alpha, const float* __restrict__ beta)
{
    int m = blockIdx.x;
    int i = threadIdx.x;
    float f = expf((float)i * (-9.210340371976184f / 64.f));
    float ang = (float)m * f;
    float s, c;
    sincosf(ang, &s, &c);
    float a1 = alpha[i], a2 = alpha[i+64];
    g_a[m*ZZ + i]      = tfr(a1*c - a2*s);
    g_a[m*ZZ + i + 64] = tfr(a2*c + a1*s);
    float b1 = beta[i],  b2 = beta[i+64];
    g_b[m*ZZ + i]      = tfr(b1*c - b2*s);
    g_b[m*ZZ + i + 64] = tfr(b2*c + b1*s);
}

// ---------------- softmax with fused rotary bias; outputs tf32-rounded ----------------
__global__ void softmax_kernel()
{
    long row = blockIdx.x;
    int  l   = (int)(row & (LL-1));
    float* p = g_qk + row * (long)CCdim;
    const float* bp = g_bias + (long)l * CCdim;
    int tid = threadIdx.x;
    float4 v0 = ((const float4*)p)[tid];
    float4 v1 = ((const float4*)p)[tid+256];
    float4 b0 = ((const float4*)bp)[tid];
    float4 b1 = ((const float4*)bp)[tid+256];
    float e0 = v0.x+b0.x, e1 = v0.y+b0.y, e2 = v0.z+b0.z, e3 = v0.w+b0.w;
    float e4 = v1.x+b1.x, e5 = v1.y+b1.y, e6 = v1.z+b1.z, e7 = v1.w+b1.w;
    float mx = fmaxf(fmaxf(fmaxf(e0,e1),fmaxf(e2,e3)), fmaxf(fmaxf(e4,e5),fmaxf(e6,e7)));
    #pragma unroll
    for (int o=16;o;o>>=1) mx = fmaxf(mx, __shfl_xor_sync(~0u,mx,o));
    __shared__ float shm[8], shs[8];
    int warp = tid>>5, lane = tid&31;
    if (lane==0) shm[warp] = mx;
    __syncthreads();
    mx = shm[0];
    #pragma unroll
    for (int wdx=1; wdx<8; ++wdx) mx = fmaxf(mx, shm[wdx]);
    e0 = expf(e0-mx); e1 = expf(e1-mx); e2 = expf(e2-mx); e3 = expf(e3-mx);
    e4 = expf(e4-mx); e5 = expf(e5-mx); e6 = expf(e6-mx); e7 = expf(e7-mx);
    float s = e0+e1+e2+e3+e4+e5+e6+e7;
    #pragma unroll
    for (int o=16;o;o>>=1) s += __shfl_xor_sync(~0u,s,o);
    if (lane==0) shs[warp] = s;
    __syncthreads();
    s = 0.f;
    #pragma unroll
    for (int wdx=0; wdx<8; ++wdx) s += shs[wdx];
    float inv = 1.f/s;
    ((float4*)p)[tid]     = make_float4(tfr(e0*inv), tfr(e1*inv), tfr(e2*inv), tfr(e3*inv));
    ((float4*)p)[tid+256] = make_float4(tfr(e4*inv), tfr(e5*inv), tfr(e6*inv), tfr(e7*inv));
}

// ---------------- h*r product (pre-pass for out projection), tf32-rounded ----------------
__global__ void hr_kernel()
{
    long i = (long)blockIdx.x*256 + threadIdx.x;
    float4 h = ((const float4*)g_h)[i];
    float4 r = ((const float4*)g_r)[i];
    ((float4*)g_x)[i] = make_float4(tfr(h.x*r.x), tfr(h.y*r.y), tfr(h.z*r.z), tfr(h.w*r.w));
}

// ---------------- TF32 GEMM, 128x128x16, 4-stage cp.async pipeline ----------------
// smem A stage: [m(128)][k(16)] rows of 64B; 16B chunk c swizzled: c ^= (m>>1)&3
// smem B stage (BT): [n(128)][k(16)] same swizzle
// smem B stage (NN): [k(16)][n(128)] rows of 512B; chunk c (0..31): c ^= (2k)&7
// All fragment LDS.32 patterns verified conflict-free (NN B needs the 2k swizzle).
template<int MODE, bool BT>
__global__ void __launch_bounds__(256, 2)
gemm_cp(const float* __restrict__ A, const float* __restrict__ Bm,
        int K, int lda, int ldb, long sAz, long sBz,
        float* __restrict__ Cout, int ldc, long sCz,
        const float* __restrict__ aux1, const float* __restrict__ aux2)
{
    extern __shared__ float smem[];
    float* As = smem;                      // STAGES * 2048
    float* Bs = smem + STAGES*2048;        // STAGES * 2048
    uint32_t AsU = (uint32_t)__cvta_generic_to_shared(As);
    uint32_t BsU = (uint32_t)__cvta_generic_to_shared(Bs);

    const int bz = blockIdx.z;
    A    += (long)bz * sAz;
    Bm   += (long)bz * sBz;
    Cout += (long)bz * sCz;

    const int m0 = blockIdx.y << 7, n0 = blockIdx.x << 7;
    const int tid = threadIdx.x, lane = tid & 31, wid = tid >> 5;
    const int wm4 = (wid >> 2) << 2;
    const int wn4 = (wid & 3) << 2;

    float acc[4][4][4];
    #pragma unroll
    for (int i=0;i<4;++i)
        #pragma unroll
        for (int j=0;j<4;++j)
            #pragma unroll
            for (int c=0;c<4;++c) acc[i][j][c] = 0.f;

    // ---- loader precompute: A (2 chunks/thread) ----
    const int ar0 = tid >> 2, ac0 = tid & 3;         // row 0..63, chunk 0..3
    const float* ga0 = A + (long)(m0 + ar0)*lda + ac0*4;
    const float* ga1 = ga0 + (long)64*lda;
    const uint32_t sa0 = (uint32_t)(ar0*16      + ((ac0 ^ ((ar0>>1)&3))<<2)) * 4;
    const uint32_t sa1 = (uint32_t)((ar0+64)*16 + ((ac0 ^ (((ar0+64)>>1)&3))<<2)) * 4;

    // ---- loader precompute: B ----
    const float *gb0, *gb1;
    uint32_t sb0, sb1;
    if (BT) {
        gb0 = Bm + (long)(n0 + ar0)*ldb + ac0*4;
        gb1 = gb0 + (long)64*ldb;
        sb0 = sa0; sb1 = sa1;
    } else {
        const int bk0 = tid >> 5, bc0 = tid & 31;    // row k 0..7, chunk 0..31
        gb0 = Bm + (long)bk0*ldb + n0 + bc0*4;
        gb1 = gb0 + (long)8*ldb;
        sb0 = (uint32_t)(bk0*128     + ((bc0 ^ ((2*bk0)&7))<<2)) * 4;
        sb1 = (uint32_t)((bk0+8)*128 + ((bc0 ^ ((2*bk0)&7))<<2)) * 4;  // (2(k+8))&7 == (2k)&7
    }

    const int ktiles = K >> 4;

    auto load_tile = [&](int slot, int kt){
        uint32_t aB = AsU + (uint32_t)slot*2048*4;
        uint32_t bB = BsU + (uint32_t)slot*2048*4;
        cpa16(aB + sa0, ga0 + kt*16);
        cpa16(aB + sa1, ga1 + kt*16);
        if (BT) {
            cpa16(bB + sb0, gb0 + kt*16);
            cpa16(bB + sb1, gb1 + kt*16);
        } else {
            cpa16(bB + sb0, gb0 + (long)kt*16*ldb);
            cpa16(bB + sb1, gb1 + (long)kt*16*ldb);
        }
    };

    auto comp = [&](int slot){
        const float* sA = As + slot*2048;
        const float* sB = Bs + slot*2048;
        #pragma unroll
        for (int ks=0; ks<2; ++ks) {
            uint32_t af[4][4], bf[4][2];
            #pragma unroll
            for (int mt=0; mt<4; ++mt) {
                int mr0 = (wm4+mt)*16 + (lane>>2);
                int mr1 = mr0 + 8;
                int s0 = (mr0>>1)&3, s1 = (mr1>>1)&3;
                const float* p0 = sA + mr0*16 + (lane&3);
                const float* p1 = sA + mr1*16 + (lane&3);
                af[mt][0] = __float_as_uint(p0[((2*ks+0)^s0)<<2]);
                af[mt][1] = __float_as_uint(p1[((2*ks+0)^s1)<<2]);
                af[mt][2] = __float_as_uint(p0[((2*ks+1)^s0)<<2]);
                af[mt][3] = __float_as_uint(p1[((2*ks+1)^s1)<<2]);
            }
            #pragma unroll
            for (int nt=0; nt<4; ++nt) {
                if (BT) {
                    int nr = (wn4+nt)*8 + (lane>>2);
                    int s = (nr>>1)&3;
                    const float* p = sB + nr*16 + (lane&3);
                    bf[nt][0] = __float_as_uint(p[((2*ks+0)^s)<<2]);
                    bf[nt][1] = __float_as_uint(p[((2*ks+1)^s)<<2]);
                } else {
                    int nn = (wn4+nt)*8 + (lane>>2);
                    int cn = nn>>2, j = nn&3;
                    int k0r = ks*8 + (lane&3);
                    int sw = (2*k0r)&7;
                    bf[nt][0] = __float_as_uint(sB[k0r*128     + ((cn^sw)<<2) + j]);
                    bf[nt][1] = __float_as_uint(sB[(k0r+4)*128 + ((cn^sw)<<2) + j]);
                }
            }
            #pragma unroll
            for (int mt=0; mt<4; ++mt)
                #pragma unroll
                for (int nt=0; nt<4; ++nt)
                    mma8(acc[mt][nt], af[mt], bf[nt]);
        }
    };

    // prologue: tiles 0..STAGES-2  (all GEMMs here have ktiles >= 8 > STAGES-1)
    #pragma unroll
    for (int s=0; s<STAGES-1; ++s) { load_tile(s, s); cpa_commit(); }

    for (int kt=0; kt<ktiles; ++kt) {
        cpa_wait<STAGES-2>();          // tile kt landed
        __syncthreads();               // everyone done with tile kt-1 (slot to be overwritten)
        int nk = kt + STAGES - 1;
        if (nk < ktiles) load_tile(nk & (STAGES-1), nk);
        cpa_commit();                  // always commit to keep group counts aligned
        comp(kt & (STAGES-1));
    }

    // ---- epilogue ----
    #pragma unroll
    for (int mt=0; mt<4; ++mt) {
        #pragma unroll
        for (int ci2=0; ci2<2; ++ci2) {
            int m = m0 + (wm4+mt)*16 + (lane>>2) + ci2*8;
            #pragma unroll
            for (int nt=0; nt<4; ++nt) {
                #pragma unroll
                for (int cj=0; cj<2; ++cj) {
                    int n = n0 + (wn4+nt)*8 + ((lane&3)<<1) + cj;
                    float v = acc[mt][nt][ci2*2+cj];
                    if (MODE==0) {
                        v += aux1[n];
                        if (n < DD)            g_u[(long)m*DD + n]        = sigmoidf_(v);
                        else if (n < 2*DD)     g_r[(long)m*DD + (n-DD)]   = siluf_(v);
                        else                   g_q[(long)m*ZZ + (n-2*DD)] = tfr(v * 0.08838834764831845f);
                    } else if (MODE==1) {
                        Cout[(long)m*ldc + n] = v;
                    } else if (MODE==2) {
                        Cout[(long)m*ldc + n] = tfr(v + aux1[n]);
                    } else if (MODE==3) {
                        Cout[(long)m*ldc + n] = tfr(siluf_(v + aux1[n]));
                    } else { // MODE 4: gated residual output
                        float t = siluf_(v + aux1[n]);
                        long idx = (long)m*DD + n;
                        float res = aux2[idx];
                        Cout[idx] = res + g_u[idx]*(t - res);
                    }
                }
            }
        }
    }
}

// ---------------- launch ----------------
extern "C" void kernel_launch(void* const* d_in, const int* in_sizes, int n_in,
                              void* d_out, int out_size)
{
    const float* query   = (const float*)d_in[0];
    const float* key_seq = (const float*)d_in[1];
    const float* value   = (const float*)d_in[2];
    const float* wq      = (const float*)d_in[3];
    const float* bq      = (const float*)d_in[4];
    const float* wk      = (const float*)d_in[5];
    const float* bk      = (const float*)d_in[6];
    const float* wv      = (const float*)d_in[7];
    const float* bv      = (const float*)d_in[8];
    const float* wh      = (const float*)d_in[9];
    const float* bh      = (const float*)d_in[10];
    const float* ln_w    = (const float*)d_in[11];
    const float* ln_b    = (const float*)d_in[12];
    const float* alpha   = (const float*)d_in[13];
    const float* beta    = (const float*)d_in[14];
    float* out = (float*)d_out;

    float *p_x, *p_q, *p_k, *p_v, *p_h, *p_a, *p_b, *p_bias, *p_qk;
    cudaGetSymbolAddress((void**)&p_x,   g_x);
    cudaGetSymbolAddress((void**)&p_q,   g_q);
    cudaGetSymbolAddress((void**)&p_k,   g_k);
    cudaGetSymbolAddress((void**)&p_v,   g_v);
    cudaGetSymbolAddress((void**)&p_h,   g_h);
    cudaGetSymbolAddress((void**)&p_a,   g_a);
    cudaGetSymbolAddress((void**)&p_b,   g_b);
    cudaGetSymbolAddress((void**)&p_bias,g_bias);
    cudaGetSymbolAddress((void**)&p_qk,  g_qk);

    static bool attr_done = false;
    if (!attr_done) {
        cudaFuncSetAttribute((const void*)gemm_cp<0,true >, cudaFuncAttributeMaxDynamicSharedMemorySize, SMEM_BYTES);
        cudaFuncSetAttribute((const void*)gemm_cp<1,true >, cudaFuncAttributeMaxDynamicSharedMemorySize, SMEM_BYTES);
        cudaFuncSetAttribute((const void*)gemm_cp<1,false>, cudaFuncAttributeMaxDynamicSharedMemorySize, SMEM_BYTES);
        cudaFuncSetAttribute((const void*)gemm_cp<2,true >, cudaFuncAttributeMaxDynamicSharedMemorySize, SMEM_BYTES);
        cudaFuncSetAttribute((const void*)gemm_cp<3,true >, cudaFuncAttributeMaxDynamicSharedMemorySize, SMEM_BYTES);
        cudaFuncSetAttribute((const void*)gemm_cp<4,true >, cudaFuncAttributeMaxDynamicSharedMemorySize, SMEM_BYTES);
        attr_done = true;
    }

    // 1. LayerNorm
    ln_kernel<<<M1, 256>>>(query, ln_w, ln_b, p_x);
    // 2. rotary a/b tables
    rotab_kernel<<<LL, 64>>>(alpha, beta);
    // 3. base projection: u / r / q  (8192 x 2176 x 1024)
    gemm_cp<0,true><<<dim3(EE/128, M1/128, 1), 256, SMEM_BYTES>>>(
        p_x, wq, DD, DD, DD, 0, 0, nullptr, 0, 0, bq, nullptr);
    // 4. k projection (8192 x 128 x 1024)
    gemm_cp<2,true><<<dim3(1, M1/128, 1), 256, SMEM_BYTES>>>(
        key_seq, wk, DD, DD, DD, 0, 0, p_k, ZZ, 0, bk, nullptr);
    // 5. v projection + silu (8192 x 1024 x 1024)
    gemm_cp<3,true><<<dim3(DD/128, M1/128, 1), 256, SMEM_BYTES>>>(
        value, wv, DD, DD, DD, 0, 0, p_v, DD, 0, bv, nullptr);
    // 6. rotary bias matrix (2048 x 2048 x 128)
    gemm_cp<1,true><<<dim3(CCdim/128, LL/128, 1), 256, SMEM_BYTES>>>(
        p_a, p_b, ZZ, ZZ, ZZ, 0, 0, p_bias, CCdim, 0, nullptr, nullptr);
    // 7. QK^T batched over B (2048 x 2048 x 128 per batch)
    gemm_cp<1,true><<<dim3(CCdim/128, LL/128, BB), 256, SMEM_BYTES>>>(
        p_q, p_k, ZZ, BB*ZZ, BB*ZZ, (long)ZZ, (long)ZZ,
        p_qk, CCdim, (long)LL*CCdim, nullptr, nullptr);
    // 8. softmax with fused bias (in place on g_qk)
    softmax_kernel<<<BB*LL, 256>>>();
    // 9. attn @ v batched (2048 x 1024 x 2048 per batch) — NN gemm
    gemm_cp<1,false><<<dim3(DD/128, LL/128, BB), 256, SMEM_BYTES>>>(
        p_qk, p_v, CCdim, CCdim, BB*DD, (long)LL*CCdim, (long)DD,
        p_h, BB*DD, (long)DD, nullptr, nullptr);
    // 9.5 h*r product into g_x (g_x free after base projection)
    hr_kernel<<<M1*DD/1024, 256>>>();
    // 10. output projection with fused silu and gated residual
    gemm_cp<4,true><<<dim3(DD/128, M1/128, 1), 256, SMEM_BYTES>>>(
        p_x, wh, DD, DD, DD, 0, 0, out, DD, 0, bh, query);
}